// round 15
// baseline (speedup 1.0000x reference)
#include <cuda_runtime.h>
#include <cuda_bf16.h>
#include <cstddef>
#include <cstdint>

#define Bsz 64
#define Sq  512
#define Isz 512
#define Hsz 1024
#define G3  3072   // 3*Hsz

// Scratch (static device allocations; no cudaMalloc anywhere)
__device__ float g_xg[(size_t)Sq * Bsz * G3];            // x_gates [s][b][g]
__device__ float g_h[2][Bsz * Hsz];                      // h ping-pong [ping][b][j] (tf32-valid fp32)
__device__ float g_Atf[(size_t)Bsz * Sq * Isz];          // inputs as tf32 [m][k]
__device__ float g_Wtf[(size_t)G3 * Isz];                // Wih as tf32 [n][k]
__device__ int   g_flags[Sq * 8];                        // per-(step,window) producer counters

// ---------------------------------------------------------------------------
// helpers
// ---------------------------------------------------------------------------
__device__ __forceinline__ uint32_t smem_u32(const void* p) {
    uint32_t a;
    asm("{ .reg .u64 t; cvta.to.shared.u64 t, %1; cvt.u32.u64 %0, t; }"
        : "=r"(a) : "l"(p));
    return a;
}
__device__ __forceinline__ void cpa16(uint32_t sdst, const void* gp) {
    asm volatile("cp.async.cg.shared.global [%0], [%1], 16;\n"
                 :: "r"(sdst), "l"(gp) : "memory");
}
__device__ __forceinline__ void ldm4(uint32_t& r0, uint32_t& r1,
                                     uint32_t& r2, uint32_t& r3, uint32_t addr) {
    asm volatile("ldmatrix.sync.aligned.m8n8.x4.shared.b16 {%0,%1,%2,%3}, [%4];"
                 : "=r"(r0), "=r"(r1), "=r"(r2), "=r"(r3) : "r"(addr));
}
// single-chain TF32 MMA: m16n8k8 (base ISA sm_80+)
__device__ __forceinline__ void mma_tf32(float& d0, float& d1, float& d2, float& d3,
                                         uint32_t a0, uint32_t a1, uint32_t a2, uint32_t a3,
                                         uint32_t b0, uint32_t b1) {
    asm volatile(
        "mma.sync.aligned.m16n8k8.row.col.f32.tf32.tf32.f32 "
        "{%0,%1,%2,%3}, {%4,%5,%6,%7}, {%8,%9}, {%0,%1,%2,%3};"
        : "+f"(d0), "+f"(d1), "+f"(d2), "+f"(d3)
        : "r"(a0), "r"(a1), "r"(a2), "r"(a3), "r"(b0), "r"(b1));
}
__device__ __forceinline__ uint32_t f2tf32(float f) {
    uint32_t r;
    asm("cvt.rna.tf32.f32 %0, %1;" : "=r"(r) : "f"(f));
    return r;
}

// ---------------------------------------------------------------------------
// fp32 -> tf32-valid fp32 (round-to-nearest into tf32 grid), vectorized, once
// ---------------------------------------------------------------------------
__global__ void tf32_cvt_kernel(const float* __restrict__ src,
                                float* __restrict__ dst)
{
    size_t i = (size_t)blockIdx.x * blockDim.x + threadIdx.x;   // float4 index
    float4 v = ((const float4*)src)[i];
    uint4 o;
    o.x = f2tf32(v.x); o.y = f2tf32(v.y); o.z = f2tf32(v.z); o.w = f2tf32(v.w);
    ((uint4*)dst)[i] = o;
}

// h0 fp32 [b][j] -> tf32-valid fp32 into ping buffer 0
__global__ void h0_prep_kernel(const float* __restrict__ h0,
                               float* __restrict__ hdst)
{
    int idx = blockIdx.x * blockDim.x + threadIdx.x;
    ((uint32_t*)hdst)[idx] = f2tf32(h0[idx]);
}

// ---------------------------------------------------------------------------
// Kernel 1: x_gates = inputs @ W_ih^T + bias_ih, single-chain TF32 (proven R14)
// ---------------------------------------------------------------------------
#define XROWB 144u
#define XHALF (128u * XROWB)
#define XBUF  (2u * XHALF)
#define XGEMM_SMEM (2u * XBUF)

extern __shared__ char xsmem[];

__global__ __launch_bounds__(256) void xgemm_mma_kernel(
    const float* __restrict__ Atf,
    const float* __restrict__ Wtf,
    const float* __restrict__ bias,
    float* __restrict__ xg)
{
    const uint32_t sb = smem_u32(xsmem);
    const int t    = threadIdx.x;
    const int wid  = t >> 5;
    const int lane = t & 31;
    const int m0   = blockIdx.y * 128;
    const int n0   = blockIdx.x * 128;
    const int wm   = (wid >> 2) * 64;
    const int wn   = (wid & 3) * 32;

    const int sub = lane >> 3;
    const uint32_t a_lane_off =
        (uint32_t)(((lane & 7) + ((sub & 1) << 3)) * XROWB + ((sub >> 1) << 4));
    const int bg   = lane >> 2;
    const int btid = lane & 3;

    float acc[4][4][4] = {};

    auto stage = [&](int w, int buf) {
        #pragma unroll
        for (int i = 0; i < 8; i++) {
            int c   = t + 256 * i;
            int op  = c >> 10;
            int rem = c & 1023;
            int row = rem >> 3;
            int q   = rem & 7;
            const float* src = (op ? Wtf + (size_t)(n0 + row) * Isz
                                   : Atf + (size_t)(m0 + row) * Isz)
                               + w * 32 + q * 4;
            cpa16(sb + (uint32_t)buf * XBUF + (uint32_t)op * XHALF
                     + (uint32_t)(row * XROWB + q * 16), src);
        }
        asm volatile("cp.async.commit_group;\n" ::: "memory");
    };

    stage(0, 0);

    #pragma unroll 1
    for (int w = 0; w < 16; w++) {
        if (w < 15) {
            stage(w + 1, (w + 1) & 1);
            asm volatile("cp.async.wait_group 1;\n" ::: "memory");
        } else {
            asm volatile("cp.async.wait_group 0;\n" ::: "memory");
        }
        __syncthreads();

        const uint32_t bufb = sb + (uint32_t)(w & 1) * XBUF;
        const uint32_t* brow[4];
        #pragma unroll
        for (int ni = 0; ni < 4; ni++)
            brow[ni] = (const uint32_t*)(xsmem + (w & 1) * XBUF + XHALF
                                         + (wn + ni * 8 + bg) * XROWB);

        #pragma unroll
        for (int kt = 0; kt < 4; kt++) {
            uint32_t b0[4], b1[4];
            #pragma unroll
            for (int ni = 0; ni < 4; ni++) {
                b0[ni] = brow[ni][kt * 8 + btid];
                b1[ni] = brow[ni][kt * 8 + btid + 4];
            }
            #pragma unroll
            for (int mi = 0; mi < 4; mi++) {
                uint32_t abase = bufb + a_lane_off
                               + (uint32_t)((wm + mi * 16) * XROWB + kt * 32);
                uint32_t a0, a1, a2, a3;
                ldm4(a0, a1, a2, a3, abase);
                #pragma unroll
                for (int ni = 0; ni < 4; ni++) {
                    float* d = acc[mi][ni];
                    mma_tf32(d[0], d[1], d[2], d[3], a0, a1, a2, a3, b0[ni], b1[ni]);
                }
            }
        }
        __syncthreads();
    }

    #pragma unroll
    for (int ni = 0; ni < 4; ni++) {
        int nn = n0 + wn + ni * 8 + 2 * (lane & 3);
        float b0 = bias[nn], b1 = bias[nn + 1];
        #pragma unroll
        for (int mi = 0; mi < 4; mi++) {
            const float* d = acc[mi][ni];
            int m = m0 + wm + mi * 16 + (lane >> 2);
            int s = m & (Sq - 1), b = m >> 9;
            *(float2*)(xg + (size_t)s * (Bsz * G3) + (size_t)b * G3 + nn) =
                make_float2(d[0] + b0, d[1] + b1);
            int m2 = m + 8;
            int s2 = m2 & (Sq - 1), b2 = m2 >> 9;
            *(float2*)(xg + (size_t)s2 * (Bsz * G3) + (size_t)b2 * G3 + nn) =
                make_float2(d[2] + b0, d[3] + b1);
        }
    }
}

// ---------------------------------------------------------------------------
// Kernel 2: PERSISTENT TF32 scan with PER-WINDOW PRODUCER FLAGS.
//   - warps 12-15 own all staging AND all flag polling (lane-0 .cg poll
//     + nanosleep backoff, then syncwarp + threadfence: fence-fence sync)
//   - compute warps (0-11) never touch flags or the LSU staging bursts
//   - rotated window order: block consumes its own-produced window LAST
//   - producers: epilogue writers threadfence, bar.sync, t0 relaxed atomicAdd
//   - ring-2 h safe: reaching step s+1 epilogue requires all step-s epilogues
// ---------------------------------------------------------------------------
#define OFF_D   0u
#define OFF_W   8192u
#define WROWB   4112u
#define OFF_H   (OFF_W + 24u * WROWB)    // 106880
#define HROWB   528u
#define HBUF    (64u * HROWB)            // 33792
#define SCAN_SMEM (OFF_H + 3u * HBUF)    // 208256 B

extern __shared__ char smem_raw[];

__global__ __launch_bounds__(512, 1) void gru_scan_kernel(
    const float* __restrict__ xg,
    const float* __restrict__ Whh,
    const float* __restrict__ bhh,
    float* __restrict__ hbuf,            // g_h base: [2][B*H]
    float* __restrict__ out,
    int* __restrict__ flags)             // [Sq][8]
{
    const uint32_t sb = smem_u32(smem_raw);
    const int t    = threadIdx.x;
    const int wid  = t >> 5;
    const int lane = t & 31;
    const int j0   = blockIdx.x * 8;
    const int wown   = blockIdx.x >> 4;          // window this block produces
    const int wstart = (wown + 1) & 7;           // consume own window last

    // ---- W -> smem as tf32-valid fp32 (once) ----
    #pragma unroll
    for (int i = 0; i < 48; i++) {
        int idx = t + 512 * i;
        int r = idx >> 10;
        int k = idx & 1023;
        int gate = r >> 3, jr = r & 7;
        float v = Whh[(size_t)(gate * Hsz + j0 + jr) * Hsz + k];
        *(uint32_t*)(smem_raw + OFF_W + r * WROWB + k * 4) = f2tf32(v);
    }
    __syncthreads();

    const int nt = wid >> 2;              // 0..2 gate tile (warps 0-11 compute)
    const int mt = wid & 3;               // 0..3 batch tile
    const int sub   = lane >> 3;
    const int a_row = mt * 16 + (lane & 7) + ((sub & 1) << 3);
    const uint32_t a_off = (uint32_t)(a_row * HROWB + ((sub >> 1) << 4));
    const int bg   = lane >> 2;
    const int btid = lane & 3;
    const uint32_t* wrow_base =
        (const uint32_t*)(smem_raw + OFF_W + (nt * 8 + bg) * WROWB);

    float bhr[8], bhz[8], bhn[8];
    if (t < 64) {
        #pragma unroll
        for (int jj = 0; jj < 8; jj++) {
            bhr[jj] = bhh[j0 + jj];
            bhz[jj] = bhh[Hsz + j0 + jj];
            bhn[jj] = bhh[2 * Hsz + j0 + jj];
        }
    }

    float* Dp = (float*)(smem_raw + OFF_D);
    const int lt = t & 127;               // staging lane id (warps 12-15)

    for (int s = 0; s < Sq; s++) {
        const int pin  = s & 1, pout = (s + 1) & 1;
        const float* hin  = hbuf + (size_t)pin  * (Bsz * Hsz);
        float*       hout = hbuf + (size_t)pout * (Bsz * Hsz);
        const float* xgs  = xg + (size_t)s * (Bsz * G3);

        float xr[8], xz[8], xn[8], hp[8];
        if (t < 64) {
            const float* xb = xgs + (size_t)t * G3 + j0;
            float4 v0 = __ldg((const float4*)xb);
            float4 v1 = __ldg((const float4*)(xb + 4));
            xr[0]=v0.x; xr[1]=v0.y; xr[2]=v0.z; xr[3]=v0.w;
            xr[4]=v1.x; xr[5]=v1.y; xr[6]=v1.z; xr[7]=v1.w;
            v0 = __ldg((const float4*)(xb + Hsz));
            v1 = __ldg((const float4*)(xb + Hsz + 4));
            xz[0]=v0.x; xz[1]=v0.y; xz[2]=v0.z; xz[3]=v0.w;
            xz[4]=v1.x; xz[5]=v1.y; xz[6]=v1.z; xz[7]=v1.w;
            v0 = __ldg((const float4*)(xb + 2 * Hsz));
            v1 = __ldg((const float4*)(xb + 2 * Hsz + 4));
            xn[0]=v0.x; xn[1]=v0.y; xn[2]=v0.z; xn[3]=v0.w;
            xn[4]=v1.x; xn[5]=v1.y; xn[6]=v1.z; xn[7]=v1.w;
            // h_prev slice (t, j0..j0+8): produced by THIS block last step
            float4 h0v = __ldcg((const float4*)(hin + (size_t)t * Hsz + j0));
            float4 h1v = __ldcg((const float4*)(hin + (size_t)t * Hsz + j0 + 4));
            hp[0]=h0v.x; hp[1]=h0v.y; hp[2]=h0v.z; hp[3]=h0v.w;
            hp[4]=h1v.x; hp[5]=h1v.y; hp[6]=h1v.z; hp[7]=h1v.w;
        }

        float dA[4] = {}, dB[4] = {};

        // stage iteration i (window (wstart+i)&7 -> ring buffer i%3).
        // Executed ONLY by warps 12-15 (128 threads, 16 cp16 each).
        auto stagei = [&](int i) {
            int w = (wstart + i) & 7;
            if (s > 0) {
                const int* f = flags + s * 8 + w;
                if (lane == 0) {
                    int v = 0;
                    #pragma unroll 1
                    for (int it = 0; it < 8000000; it++) {
                        asm volatile("ld.global.cg.s32 %0, [%1];"
                                     : "=r"(v) : "l"(f) : "memory");
                        if (v >= 16) break;
                        __nanosleep(64);
                    }
                }
                __syncwarp();
                __threadfence();          // consumer-side fence (fence-fence sync)
            }
            int buf = i % 3;
            #pragma unroll
            for (int q = 0; q < 16; q++) {
                int c   = lt + 128 * q;          // 0..2047 cp16 slots
                int row = c >> 5;                // batch row 0..63
                int cq  = c & 31;                // 16B chunk in 512B
                const char* src = (const char*)hin + (size_t)row * 4096
                                  + w * 512 + cq * 16;
                cpa16(sb + OFF_H + (uint32_t)buf * HBUF
                         + row * HROWB + cq * 16, src);
            }
            asm volatile("cp.async.commit_group;\n" ::: "memory");
        };

        if (wid >= 12) { stagei(0); stagei(1); }

        #pragma unroll 1
        for (int i = 0; i < 8; i++) {
            if (wid >= 12) {
                if (i < 7) asm volatile("cp.async.wait_group 1;\n" ::: "memory");
                else       asm volatile("cp.async.wait_group 0;\n" ::: "memory");
            }
            __syncthreads();   // buffer i%3 ready; all warps done with iter i-1

            if (wid < 12) {
                int w = (wstart + i) & 7;
                const uint32_t abase = sb + OFF_H + (uint32_t)(i % 3) * HBUF + a_off;
                const uint32_t* wrow = wrow_base + w * 128;
                #pragma unroll
                for (int kt = 0; kt < 16; kt++) {
                    float* d = (kt & 1) ? dB : dA;
                    uint32_t a0, a1, a2, a3;
                    ldm4(a0, a1, a2, a3, abase + kt * 32);
                    uint32_t b0 = wrow[kt * 8 + btid];
                    uint32_t b1 = wrow[kt * 8 + btid + 4];
                    mma_tf32(d[0], d[1], d[2], d[3], a0, a1, a2, a3, b0, b1);
                }
            } else if (i + 2 < 8) {
                stagei(i + 2);   // writes buf (i+2)%3 == (i-1)%3: free after sync
            }
        }

        if (wid < 12) {
            int m  = mt * 16 + (lane >> 2);
            int nc = nt * 8 + 2 * (lane & 3);
            Dp[m * 26 + nc]           = dA[0] + dB[0];
            Dp[m * 26 + nc + 1]       = dA[1] + dB[1];
            Dp[(m + 8) * 26 + nc]     = dA[2] + dB[2];
            Dp[(m + 8) * 26 + nc + 1] = dA[3] + dB[3];
        }
        __syncthreads();

        if (t < 64) {
            float hnv[8];
            uint32_t ht[8];
            #pragma unroll
            for (int jj = 0; jj < 8; jj++) {
                float ar = Dp[t * 26 + jj];
                float az = Dp[t * 26 + 8 + jj];
                float an = Dp[t * 26 + 16 + jj];
                float r = 1.f / (1.f + expf(-(xr[jj] + ar + bhr[jj])));
                float z = 1.f / (1.f + expf(-(xz[jj] + az + bhz[jj])));
                float n = tanhf(xn[jj] + r * (an + bhn[jj]));
                float h = (1.f - z) * n + z * hp[jj];
                hnv[jj] = h;
                ht[jj]  = f2tf32(h);
            }
            float* op = out + (size_t)t * Sq * Hsz + (size_t)s * Hsz + j0;
            *(float4*)op       = make_float4(hnv[0], hnv[1], hnv[2], hnv[3]);
            *(float4*)(op + 4) = make_float4(hnv[4], hnv[5], hnv[6], hnv[7]);
            *(uint4*)(hout + (size_t)t * Hsz + j0)     = *(uint4*)ht;
            *(uint4*)(hout + (size_t)t * Hsz + j0 + 4) = *(uint4*)(ht + 4);
            if (s == Sq - 1) {
                float* hn = out + (size_t)Bsz * Sq * Hsz + (size_t)t * Hsz + j0;
                *(float4*)hn       = make_float4(hnv[0], hnv[1], hnv[2], hnv[3]);
                *(float4*)(hn + 4) = make_float4(hnv[4], hnv[5], hnv[6], hnv[7]);
            }
            __threadfence();   // producer-side fence (device scope)
        }

        __syncthreads();       // order t0's publish after all writers' fences
        if (t == 0 && s + 1 < Sq)
            atomicAdd(flags + (s + 1) * 8 + wown, 1);   // relaxed publish
    }
}

// ---------------------------------------------------------------------------
// kernel_launch (graph-capturable: kernels + one async memset)
// ---------------------------------------------------------------------------
extern "C" void kernel_launch(void* const* d_in, const int* in_sizes, int n_in,
                              void* d_out, int out_size)
{
    const float* inputs = (const float*)d_in[0];
    const float* h0     = (const float*)d_in[1];
    const float* Wih    = (const float*)d_in[2];
    const float* Whh    = (const float*)d_in[3];
    const float* bih    = (const float*)d_in[4];
    const float* bhh    = (const float*)d_in[5];
    float* out = (float*)d_out;

    float *xg = nullptr, *hb = nullptr, *atf = nullptr, *wtf = nullptr;
    int* flags = nullptr;
    cudaGetSymbolAddress((void**)&xg,  g_xg);
    cudaGetSymbolAddress((void**)&hb,  g_h);
    cudaGetSymbolAddress((void**)&atf, g_Atf);
    cudaGetSymbolAddress((void**)&wtf, g_Wtf);
    cudaGetSymbolAddress((void**)&flags, g_flags);

    cudaFuncSetAttribute(gru_scan_kernel,
                         cudaFuncAttributeMaxDynamicSharedMemorySize, SCAN_SMEM);
    cudaFuncSetAttribute(xgemm_mma_kernel,
                         cudaFuncAttributeMaxDynamicSharedMemorySize, XGEMM_SMEM);

    // zero producer flags for this run (capturable memset node, 16 KB)
    cudaMemsetAsync(flags, 0, (size_t)Sq * 8 * sizeof(int));

    // Phase A: convert inputs/Wih/h0 to tf32 grid, then TF32 input GEMM
    tf32_cvt_kernel<<<(int)((size_t)Bsz * Sq * Isz / 4 / 256), 256>>>(inputs, atf);
    tf32_cvt_kernel<<<(int)((size_t)G3 * Isz / 4 / 256), 256>>>(Wih, wtf);
    h0_prep_kernel<<<(Bsz * Hsz) / 256, 256>>>(h0, hb);

    dim3 ggrid(G3 / 128, (Bsz * Sq) / 128);   // (24, 256)
    xgemm_mma_kernel<<<ggrid, 256, XGEMM_SMEM>>>(atf, wtf, bih, xg);

    // Phase B: whole scan in ONE persistent kernel with per-window flags
    gru_scan_kernel<<<128, 512, SCAN_SMEM>>>(xg, Whh, bhh, hb, out, flags);
}

// round 16
// speedup vs baseline: 1.0901x; 1.0901x over previous
#include <cuda_runtime.h>
#include <cuda_bf16.h>
#include <cstddef>
#include <cstdint>

#define Bsz 64
#define Sq  512
#define Isz 512
#define Hsz 1024
#define G3  3072   // 3*Hsz

// Scratch (static device allocations; no cudaMalloc anywhere)
__device__ float g_xg[(size_t)Sq * Bsz * G3];            // x_gates [s][b][g]
__device__ float g_h[2][Bsz * Hsz];                      // h ping-pong [ping][b][j] (tf32-valid fp32)
__device__ float g_Wtf[(size_t)G3 * Isz];                // Wih as tf32 [n][k]

// two-level grid barrier (monotonic counters: no reset, graph-replay safe)
struct PadCtr { unsigned v; unsigned pad[31]; };
__device__ PadCtr  g_sub[8];        // 16 arrivals each per step
__device__ unsigned g_root;         // 8 arrivals per step
__device__ unsigned g_bar_phase;    // +1 per step

// ---------------------------------------------------------------------------
// helpers
// ---------------------------------------------------------------------------
__device__ __forceinline__ uint32_t smem_u32(const void* p) {
    uint32_t a;
    asm("{ .reg .u64 t; cvta.to.shared.u64 t, %1; cvt.u32.u64 %0, t; }"
        : "=r"(a) : "l"(p));
    return a;
}
__device__ __forceinline__ void cpa16(uint32_t sdst, const void* gp) {
    asm volatile("cp.async.cg.shared.global [%0], [%1], 16;\n"
                 :: "r"(sdst), "l"(gp) : "memory");
}
__device__ __forceinline__ void ldm4(uint32_t& r0, uint32_t& r1,
                                     uint32_t& r2, uint32_t& r3, uint32_t addr) {
    asm volatile("ldmatrix.sync.aligned.m8n8.x4.shared.b16 {%0,%1,%2,%3}, [%4];"
                 : "=r"(r0), "=r"(r1), "=r"(r2), "=r"(r3) : "r"(addr));
}
// single-chain TF32 MMA: m16n8k8 (base ISA sm_80+). HW uses the top 19 bits
// of each fp32 operand (tf32 truncation) — raw fp32 inputs are accepted.
__device__ __forceinline__ void mma_tf32(float& d0, float& d1, float& d2, float& d3,
                                         uint32_t a0, uint32_t a1, uint32_t a2, uint32_t a3,
                                         uint32_t b0, uint32_t b1) {
    asm volatile(
        "mma.sync.aligned.m16n8k8.row.col.f32.tf32.tf32.f32 "
        "{%0,%1,%2,%3}, {%4,%5,%6,%7}, {%8,%9}, {%0,%1,%2,%3};"
        : "+f"(d0), "+f"(d1), "+f"(d2), "+f"(d3)
        : "r"(a0), "r"(a1), "r"(a2), "r"(a3), "r"(b0), "r"(b1));
}
__device__ __forceinline__ uint32_t f2tf32(float f) {
    uint32_t r;
    asm("cvt.rna.tf32.f32 %0, %1;" : "=r"(r) : "f"(f));
    return r;
}

// ---------------------------------------------------------------------------
// fp32 -> tf32-valid fp32 (round-to-nearest into tf32 grid), once (Wih only)
// ---------------------------------------------------------------------------
__global__ void tf32_cvt_kernel(const float* __restrict__ src,
                                float* __restrict__ dst)
{
    size_t i = (size_t)blockIdx.x * blockDim.x + threadIdx.x;   // float4 index
    float4 v = ((const float4*)src)[i];
    uint4 o;
    o.x = f2tf32(v.x); o.y = f2tf32(v.y); o.z = f2tf32(v.z); o.w = f2tf32(v.w);
    ((uint4*)dst)[i] = o;
}

// h0 fp32 [b][j] -> tf32-valid fp32 into ping buffer 0
__global__ void h0_prep_kernel(const float* __restrict__ h0,
                               float* __restrict__ hdst)
{
    int idx = blockIdx.x * blockDim.x + threadIdx.x;
    ((uint32_t*)hdst)[idx] = f2tf32(h0[idx]);
}

// ---------------------------------------------------------------------------
// Kernel 1: x_gates = inputs @ W_ih^T + bias_ih, single-chain TF32 (proven R14;
// A read directly from raw fp32 inputs — HW tf32 truncation)
// ---------------------------------------------------------------------------
#define XROWB 144u
#define XHALF (128u * XROWB)
#define XBUF  (2u * XHALF)
#define XGEMM_SMEM (2u * XBUF)

extern __shared__ char xsmem[];

__global__ __launch_bounds__(256) void xgemm_mma_kernel(
    const float* __restrict__ A,         // inputs [B*S][I] (row m: b=m>>9, s=m&511)
    const float* __restrict__ Wtf,
    const float* __restrict__ bias,
    float* __restrict__ xg)
{
    const uint32_t sb = smem_u32(xsmem);
    const int t    = threadIdx.x;
    const int wid  = t >> 5;
    const int lane = t & 31;
    const int m0   = blockIdx.y * 128;
    const int n0   = blockIdx.x * 128;
    const int wm   = (wid >> 2) * 64;
    const int wn   = (wid & 3) * 32;

    const int sub = lane >> 3;
    const uint32_t a_lane_off =
        (uint32_t)(((lane & 7) + ((sub & 1) << 3)) * XROWB + ((sub >> 1) << 4));
    const int bg   = lane >> 2;
    const int btid = lane & 3;

    float acc[4][4][4] = {};

    auto stage = [&](int w, int buf) {
        #pragma unroll
        for (int i = 0; i < 8; i++) {
            int c   = t + 256 * i;
            int op  = c >> 10;
            int rem = c & 1023;
            int row = rem >> 3;
            int q   = rem & 7;
            const float* src = (op ? Wtf + (size_t)(n0 + row) * Isz
                                   : A   + (size_t)(m0 + row) * Isz)
                               + w * 32 + q * 4;
            cpa16(sb + (uint32_t)buf * XBUF + (uint32_t)op * XHALF
                     + (uint32_t)(row * XROWB + q * 16), src);
        }
        asm volatile("cp.async.commit_group;\n" ::: "memory");
    };

    stage(0, 0);

    #pragma unroll 1
    for (int w = 0; w < 16; w++) {
        if (w < 15) {
            stage(w + 1, (w + 1) & 1);
            asm volatile("cp.async.wait_group 1;\n" ::: "memory");
        } else {
            asm volatile("cp.async.wait_group 0;\n" ::: "memory");
        }
        __syncthreads();

        const uint32_t bufb = sb + (uint32_t)(w & 1) * XBUF;
        const uint32_t* brow[4];
        #pragma unroll
        for (int ni = 0; ni < 4; ni++)
            brow[ni] = (const uint32_t*)(xsmem + (w & 1) * XBUF + XHALF
                                         + (wn + ni * 8 + bg) * XROWB);

        #pragma unroll
        for (int kt = 0; kt < 4; kt++) {
            uint32_t b0[4], b1[4];
            #pragma unroll
            for (int ni = 0; ni < 4; ni++) {
                b0[ni] = brow[ni][kt * 8 + btid];
                b1[ni] = brow[ni][kt * 8 + btid + 4];
            }
            #pragma unroll
            for (int mi = 0; mi < 4; mi++) {
                uint32_t abase = bufb + a_lane_off
                               + (uint32_t)((wm + mi * 16) * XROWB + kt * 32);
                uint32_t a0, a1, a2, a3;
                ldm4(a0, a1, a2, a3, abase);
                #pragma unroll
                for (int ni = 0; ni < 4; ni++) {
                    float* d = acc[mi][ni];
                    mma_tf32(d[0], d[1], d[2], d[3], a0, a1, a2, a3, b0[ni], b1[ni]);
                }
            }
        }
        __syncthreads();
    }

    #pragma unroll
    for (int ni = 0; ni < 4; ni++) {
        int nn = n0 + wn + ni * 8 + 2 * (lane & 3);
        float b0 = bias[nn], b1 = bias[nn + 1];
        #pragma unroll
        for (int mi = 0; mi < 4; mi++) {
            const float* d = acc[mi][ni];
            int m = m0 + wm + mi * 16 + (lane >> 2);
            int s = m & (Sq - 1), b = m >> 9;
            *(float2*)(xg + (size_t)s * (Bsz * G3) + (size_t)b * G3 + nn) =
                make_float2(d[0] + b0, d[1] + b1);
            int m2 = m + 8;
            int s2 = m2 & (Sq - 1), b2 = m2 >> 9;
            *(float2*)(xg + (size_t)s2 * (Bsz * G3) + (size_t)b2 * G3 + nn) =
                make_float2(d[2] + b0, d[3] + b1);
        }
    }
}

// ---------------------------------------------------------------------------
// Kernel 2: PERSISTENT single-chain TF32 scan (R14 skeleton: triple-buffered
// h windows, two-level grid barrier) + cross-step operand pipelining:
// xg[s+1] is prefetched into smem XP before the barrier, and hnv is carried
// through XP, removing the per-step xg/hp L2 latency from the critical path.
// ---------------------------------------------------------------------------
#define OFF_D   0u                       // 64 x 26 fp32 = 6656 B
#define OFF_XP  6656u                    // 64 x 32 fp32 = 8192 B (xr,xz,xn,hp)
#define OFF_W   16384u
#define WROWB   4112u                    // 1024 fp32 = 4096B + 16 pad
#define OFF_H   (OFF_W + 24u * WROWB)    // 115072
#define HROWB   528u                     // 128 fp32 = 512B + 16 pad
#define HBUF    (64u * HROWB)            // 33792
#define SCAN_SMEM (OFF_H + 3u * HBUF)    // 216448 B

extern __shared__ char smem_raw[];

__global__ __launch_bounds__(512, 1) void gru_scan_kernel(
    const float* __restrict__ xg,
    const float* __restrict__ Whh,
    const float* __restrict__ bhh,
    float* __restrict__ hbuf,            // g_h base: [2][B*H]
    float* __restrict__ out)
{
    const uint32_t sb = smem_u32(smem_raw);
    const int t    = threadIdx.x;
    const int wid  = t >> 5;
    const int lane = t & 31;
    const int j0   = blockIdx.x * 8;

    // ---- W -> smem as tf32-valid fp32 (once) ----
    #pragma unroll
    for (int i = 0; i < 48; i++) {
        int idx = t + 512 * i;            // 0..24575
        int r = idx >> 10;                // 0..23 = gate*8 + jr
        int k = idx & 1023;
        int gate = r >> 3, jr = r & 7;
        float v = Whh[(size_t)(gate * Hsz + j0 + jr) * Hsz + k];
        *(uint32_t*)(smem_raw + OFF_W + r * WROWB + k * 4) = f2tf32(v);
    }
    __syncthreads();

    unsigned base = 0;
    if (t == 0) base = *(volatile unsigned*)&g_bar_phase;

    const int nt = wid >> 2;              // 0..2 gate tile (warps 0-11 compute)
    const int mt = wid & 3;               // 0..3 batch tile
    const int sub   = lane >> 3;
    const int a_row = mt * 16 + (lane & 7) + ((sub & 1) << 3);
    const uint32_t a_off = (uint32_t)(a_row * HROWB + ((sub >> 1) << 4));
    const int bg   = lane >> 2;
    const int btid = lane & 3;
    const uint32_t* wrow_base =
        (const uint32_t*)(smem_raw + OFF_W + (nt * 8 + bg) * WROWB);

    float bhr[8], bhz[8], bhn[8];
    if (t < 64) {
        #pragma unroll
        for (int jj = 0; jj < 8; jj++) {
            bhr[jj] = bhh[j0 + jj];
            bhz[jj] = bhh[Hsz + j0 + jj];
            bhn[jj] = bhh[2 * Hsz + j0 + jj];
        }
    }

    float* Dp = (float*)(smem_raw + OFF_D);
    float* XP = (float*)(smem_raw + OFF_XP);   // per-thread slot: 32 floats

    for (int s = 0; s < Sq; s++) {
        const int pin  = s & 1, pout = (s + 1) & 1;
        const float* hin  = hbuf + (size_t)pin  * (Bsz * Hsz);
        float*       hout = hbuf + (size_t)pout * (Bsz * Hsz);

        float xr[8], xz[8], xn[8], hp[8];
        if (t < 64) {
            if (s == 0) {
                const float* xb = xg + (size_t)t * G3 + j0;   // xg[s=0]
                float4 v0 = __ldg((const float4*)xb);
                float4 v1 = __ldg((const float4*)(xb + 4));
                xr[0]=v0.x; xr[1]=v0.y; xr[2]=v0.z; xr[3]=v0.w;
                xr[4]=v1.x; xr[5]=v1.y; xr[6]=v1.z; xr[7]=v1.w;
                v0 = __ldg((const float4*)(xb + Hsz));
                v1 = __ldg((const float4*)(xb + Hsz + 4));
                xz[0]=v0.x; xz[1]=v0.y; xz[2]=v0.z; xz[3]=v0.w;
                xz[4]=v1.x; xz[5]=v1.y; xz[6]=v1.z; xz[7]=v1.w;
                v0 = __ldg((const float4*)(xb + 2 * Hsz));
                v1 = __ldg((const float4*)(xb + 2 * Hsz + 4));
                xn[0]=v0.x; xn[1]=v0.y; xn[2]=v0.z; xn[3]=v0.w;
                xn[4]=v1.x; xn[5]=v1.y; xn[6]=v1.z; xn[7]=v1.w;
                float4 h0v = __ldcg((const float4*)(hin + (size_t)t * Hsz + j0));
                float4 h1v = __ldcg((const float4*)(hin + (size_t)t * Hsz + j0 + 4));
                hp[0]=h0v.x; hp[1]=h0v.y; hp[2]=h0v.z; hp[3]=h0v.w;
                hp[4]=h1v.x; hp[5]=h1v.y; hp[6]=h1v.z; hp[7]=h1v.w;
            } else {
                const float* xp = XP + t * 32;   // prefetched last step
                #pragma unroll
                for (int q = 0; q < 2; q++) {
                    float4 a = *(const float4*)(xp + q * 4);
                    float4 b = *(const float4*)(xp + 8 + q * 4);
                    float4 c = *(const float4*)(xp + 16 + q * 4);
                    float4 d = *(const float4*)(xp + 24 + q * 4);
                    xr[q*4+0]=a.x; xr[q*4+1]=a.y; xr[q*4+2]=a.z; xr[q*4+3]=a.w;
                    xz[q*4+0]=b.x; xz[q*4+1]=b.y; xz[q*4+2]=b.z; xz[q*4+3]=b.w;
                    xn[q*4+0]=c.x; xn[q*4+1]=c.y; xn[q*4+2]=c.z; xn[q*4+3]=c.w;
                    hp[q*4+0]=d.x; hp[q*4+1]=d.y; hp[q*4+2]=d.z; hp[q*4+3]=d.w;
                }
            }
        }

        float dA[4] = {}, dB[4] = {};

        // stage window w (k in [128w,128w+128)) into ring buffer w%3
        auto stage = [&](int w) {
            int buf = w % 3;
            #pragma unroll
            for (int i = 0; i < 4; i++) {
                int c   = t + 512 * i;          // 0..2047 cp16 slots
                int row = c >> 5;               // batch row 0..63
                int cq  = c & 31;               // 16B chunk in 512B
                const char* src = (const char*)hin + (size_t)row * 4096
                                  + w * 512 + cq * 16;
                cpa16(sb + OFF_H + (uint32_t)buf * HBUF
                         + row * HROWB + cq * 16, src);
            }
            asm volatile("cp.async.commit_group;\n" ::: "memory");
        };

        stage(0);
        stage(1);

        #pragma unroll 1
        for (int w = 0; w < 8; w++) {
            if (w < 7) asm volatile("cp.async.wait_group 1;\n" ::: "memory");
            else       asm volatile("cp.async.wait_group 0;\n" ::: "memory");
            __syncthreads();   // window w data in; all warps done with iter w-1

            if (wid < 12) {
                const uint32_t abase = sb + OFF_H + (uint32_t)(w % 3) * HBUF + a_off;
                const uint32_t* wrow = wrow_base + w * 128;
                #pragma unroll
                for (int kt = 0; kt < 16; kt++) {   // 16 k8-steps per window
                    float* d = (kt & 1) ? dB : dA;
                    uint32_t a0, a1, a2, a3;
                    ldm4(a0, a1, a2, a3, abase + kt * 32);
                    uint32_t b0 = wrow[kt * 8 + btid];
                    uint32_t b1 = wrow[kt * 8 + btid + 4];
                    mma_tf32(d[0], d[1], d[2], d[3], a0, a1, a2, a3, b0, b1);
                }
            }
            // prefetch window w+2 (writes buf (w+2)%3 == (w-1)%3: free now)
            if (w + 2 < 8) stage(w + 2);
        }

        if (wid < 12) {
            int m  = mt * 16 + (lane >> 2);
            int nc = nt * 8 + 2 * (lane & 3);
            Dp[m * 26 + nc]           = dA[0] + dB[0];
            Dp[m * 26 + nc + 1]       = dA[1] + dB[1];
            Dp[(m + 8) * 26 + nc]     = dA[2] + dB[2];
            Dp[(m + 8) * 26 + nc + 1] = dA[3] + dB[3];
        }
        __syncthreads();

        if (t < 64) {
            float hnv[8];
            uint32_t ht[8];
            #pragma unroll
            for (int jj = 0; jj < 8; jj++) {
                float ar = Dp[t * 26 + jj];
                float az = Dp[t * 26 + 8 + jj];
                float an = Dp[t * 26 + 16 + jj];
                float r = 1.f / (1.f + expf(-(xr[jj] + ar + bhr[jj])));
                float z = 1.f / (1.f + expf(-(xz[jj] + az + bhz[jj])));
                float n = tanhf(xn[jj] + r * (an + bhn[jj]));
                float h = (1.f - z) * n + z * hp[jj];
                hnv[jj] = h;
                ht[jj]  = f2tf32(h);    // next step's MMA operand (rounded)
            }
            float* op = out + (size_t)t * Sq * Hsz + (size_t)s * Hsz + j0;
            *(float4*)op       = make_float4(hnv[0], hnv[1], hnv[2], hnv[3]);
            *(float4*)(op + 4) = make_float4(hnv[4], hnv[5], hnv[6], hnv[7]);
            *(uint4*)(hout + (size_t)t * Hsz + j0)     = *(uint4*)ht;
            *(uint4*)(hout + (size_t)t * Hsz + j0 + 4) = *(uint4*)(ht + 4);
            if (s == Sq - 1) {
                float* hn = out + (size_t)Bsz * Sq * Hsz + (size_t)t * Hsz + j0;
                *(float4*)hn       = make_float4(hnv[0], hnv[1], hnv[2], hnv[3]);
                *(float4*)(hn + 4) = make_float4(hnv[4], hnv[5], hnv[6], hnv[7]);
            }

            // ---- cross-step prefetch: xg[s+1] + hnv -> XP (hides L2 latency
            // behind the grid barrier; hp carried unrounded = more accurate) ----
            if (s + 1 < Sq) {
                const float* xb = xg + (size_t)(s + 1) * (Bsz * G3)
                                     + (size_t)t * G3 + j0;
                float4 a0 = __ldg((const float4*)xb);
                float4 a1 = __ldg((const float4*)(xb + 4));
                float4 b0 = __ldg((const float4*)(xb + Hsz));
                float4 b1 = __ldg((const float4*)(xb + Hsz + 4));
                float4 c0 = __ldg((const float4*)(xb + 2 * Hsz));
                float4 c1 = __ldg((const float4*)(xb + 2 * Hsz + 4));
                float* xp = XP + t * 32;
                *(float4*)(xp)      = a0;  *(float4*)(xp + 4)  = a1;
                *(float4*)(xp + 8)  = b0;  *(float4*)(xp + 12) = b1;
                *(float4*)(xp + 16) = c0;  *(float4*)(xp + 20) = c1;
                *(float4*)(xp + 24) = make_float4(hnv[0], hnv[1], hnv[2], hnv[3]);
                *(float4*)(xp + 28) = make_float4(hnv[4], hnv[5], hnv[6], hnv[7]);
            }
            __threadfence();   // release this block's h slice (device scope)
        }

        // ---- two-level grid barrier between steps ----
        __syncthreads();
        if (t == 0 && s + 1 < Sq) {
            __threadfence();
            unsigned a = atomicAdd(&g_sub[blockIdx.x & 7].v, 1u);
            bool last = false;
            if ((a & 15u) == 15u) {                       // 16th arrival here
                unsigned r = atomicAdd(&g_root, 1u);
                if ((r & 7u) == 7u) {                     // 8th sub-group
                    __threadfence();
                    atomicAdd(&g_bar_phase, 1u);
                    last = true;
                }
            }
            if (!last) {
                unsigned target = (unsigned)(s + 1);
                unsigned spins = 0;
                while ((unsigned)(*(volatile unsigned*)&g_bar_phase - base) < target) {
                    if (++spins > 200000000u) break;      // fail loud, not hung
                }
                __threadfence();
            }
        }
        __syncthreads();
    }
}

// ---------------------------------------------------------------------------
// kernel_launch (graph-capturable: kernel launches only)
// ---------------------------------------------------------------------------
extern "C" void kernel_launch(void* const* d_in, const int* in_sizes, int n_in,
                              void* d_out, int out_size)
{
    const float* inputs = (const float*)d_in[0];
    const float* h0     = (const float*)d_in[1];
    const float* Wih    = (const float*)d_in[2];
    const float* Whh    = (const float*)d_in[3];
    const float* bih    = (const float*)d_in[4];
    const float* bhh    = (const float*)d_in[5];
    float* out = (float*)d_out;

    float *xg = nullptr, *hb = nullptr, *wtf = nullptr;
    cudaGetSymbolAddress((void**)&xg,  g_xg);
    cudaGetSymbolAddress((void**)&hb,  g_h);
    cudaGetSymbolAddress((void**)&wtf, g_Wtf);

    cudaFuncSetAttribute(gru_scan_kernel,
                         cudaFuncAttributeMaxDynamicSharedMemorySize, SCAN_SMEM);
    cudaFuncSetAttribute(xgemm_mma_kernel,
                         cudaFuncAttributeMaxDynamicSharedMemorySize, XGEMM_SMEM);

    // Phase A: Wih -> tf32 grid (rna); inputs fed raw (HW truncation).
    tf32_cvt_kernel<<<(int)((size_t)G3 * Isz / 4 / 256), 256>>>(Wih, wtf);
    h0_prep_kernel<<<(Bsz * Hsz) / 256, 256>>>(h0, hb);

    dim3 ggrid(G3 / 128, (Bsz * Sq) / 128);   // (24, 256)
    xgemm_mma_kernel<<<ggrid, 256, XGEMM_SMEM>>>(inputs, wtf, bih, xg);

    // Phase B: whole scan in ONE persistent kernel (two-level barrier)
    gru_scan_kernel<<<128, 512, SCAN_SMEM>>>(xg, Whh, bhh, hb, out);
}